// round 14
// baseline (speedup 1.0000x reference)
#include <cuda_runtime.h>
#include <math.h>
#include <stdint.h>

#define C_DIM 512
#define AREA  4096
#define BATCH 4
#define GROUPS 32
#define CPG   16
#define GRP_F4 16384   // (CPG*AREA)/4 float4s per group

// ---------------- scratch (static device globals; no allocation) ----------------
__device__ float g_xn  [(size_t)BATCH * C_DIM * AREA];
__device__ float g_q   [(size_t)BATCH * C_DIM * AREA];
__device__ float g_k   [(size_t)BATCH * C_DIM * AREA];
__device__ float g_v   [(size_t)BATCH * C_DIM * AREA];
__device__ float g_ao  [(size_t)BATCH * C_DIM * AREA];
__device__ float g_attn[(size_t)BATCH * AREA * AREA];

// ---------------- GroupNorm ----------------
__global__ void groupnorm_kernel(const float* __restrict__ net,
                                 const float* __restrict__ gscale,
                                 const float* __restrict__ gbias,
                                 float* __restrict__ xn) {
    const int bg = blockIdx.x;          // 0..127
    const int b  = bg >> 5;
    const int g  = bg & 31;
    const size_t base = ((size_t)b * C_DIM + (size_t)g * CPG) * AREA;
    const float4* src4 = (const float4*)(net + base);
    float4* dst4 = (float4*)(xn + base);
    const int tid = threadIdx.x;

    float s = 0.f, ss = 0.f;
    for (int i = tid; i < GRP_F4; i += 256) {
        float4 v = src4[i];
        s  += v.x + v.y + v.z + v.w;
        ss += v.x*v.x + v.y*v.y + v.z*v.z + v.w*v.w;
    }
    __shared__ float red[512];
    red[tid] = s; red[256 + tid] = ss;
    __syncthreads();
    for (int off = 128; off > 0; off >>= 1) {
        if (tid < off) {
            red[tid]       += red[tid + off];
            red[256 + tid] += red[256 + tid + off];
        }
        __syncthreads();
    }
    const float inv_n = 1.0f / 65536.0f;
    const float mu   = red[0] * inv_n;
    const float var  = red[256] * inv_n - mu * mu;
    const float rstd = rsqrtf(var + 1e-6f);

    for (int i = tid; i < GRP_F4; i += 256) {
        const int c_local = i >> 10;
        const float sc = gscale[g * CPG + c_local] * rstd;
        const float bi = gbias[g * CPG + c_local];
        float4 v = src4[i];
        v.x = (v.x - mu) * sc + bi;
        v.y = (v.y - mu) * sc + bi;
        v.z = (v.z - mu) * sc + bi;
        v.w = (v.w - mu) * sc + bi;
        dst4[i] = v;
    }
}

// ---------------- async copy helper ----------------
__device__ __forceinline__ void cp16(uint32_t dst_smem, const void* src) {
    asm volatile("cp.async.cg.shared.global [%0], [%1], 16;\n"
                 :: "r"(dst_smem), "l"(src));
}

// ---------------- tensor-core tf32 GEMM, 3-stage cp.async, 1 sync/k-tile ----------------
// C[m,n] = alpha * sum_k Aval(m,k)*Bval(k,n) + bias[m] + resid[m,n]
// TA=0: A row-major [M,K] (K-contiguous) ; TA=1: A stored [K,M] (M-contiguous)
// TB=0: B row-major [K,N] (N-contiguous) ; TB=1: B stored [N,K] (K-contiguous)
// Block 128x128, BK=32, 256 threads (8 warps of 64x32), mma m16n8k8 tf32.
// Raw fp32 in smem; mma.tf32 truncates in hardware.
// Pipeline: fill(0),fill(1) upfront; per iter: wait_group 1 (stage t ready),
// sync, fill stage t+2 (or empty commit at tail), MMA stage t.
// Stage (t+2)%3 was last read at iter t-1 -> this iter's sync orders overwrite.
template<int TA, int TB>
__global__ __launch_bounds__(256, 2)
void gemm_p3(const float* __restrict__ A, const float* __restrict__ B,
             float* __restrict__ C,
             int M, int N, int K,
             size_t sAb, size_t sBb, size_t sCb,
             float alpha,
             const float* __restrict__ bias,
             const float* __restrict__ resid, size_t sRb) {
    constexpr int AW = (TA == 0) ? 128 * 36 : 32 * 136;   // words per A stage
    constexpr int BW = (TB == 0) ? 32 * 136 : 128 * 36;   // words per B stage
    extern __shared__ uint32_t sm[];                      // 3*(AW+BW) words

    const int tid  = threadIdx.x;
    const int warp = tid >> 5;
    const int lane = tid & 31;
    const int g    = lane >> 2;     // 0..7
    const int tg   = lane & 3;      // 0..3
    const int warpM = warp >> 2;    // 0..1  (64 rows)
    const int warpN = warp & 3;     // 0..3  (32 cols)
    const int n0 = blockIdx.x * 128;
    const int m0 = blockIdx.y * 128;
    const int bz = blockIdx.z;

    const float4* A4 = (const float4*)(A + (size_t)bz * sAb);
    const float4* B4 = (const float4*)(B + (size_t)bz * sBb);
    const int K4 = K >> 2, N4 = N >> 2, M4 = M >> 2;
    const uint32_t sb = (uint32_t)__cvta_generic_to_shared(sm);

    float acc[4][4][4];
    #pragma unroll
    for (int mt = 0; mt < 4; ++mt)
        #pragma unroll
        for (int nt = 0; nt < 4; ++nt)
            #pragma unroll
            for (int r = 0; r < 4; ++r) acc[mt][nt][r] = 0.f;

    // ---- async fill of one stage ----
    auto fill = [&](int stage, int k0) {
        const uint32_t aBase = sb + (uint32_t)(stage * AW) * 4u;
        const uint32_t bBase = sb + (uint32_t)(3 * AW + stage * BW) * 4u;
        #pragma unroll
        for (int j = 0; j < 4; ++j) {
            const int l4 = j * 256 + tid;
            if (TA == 0) {
                const int kk4 = l4 & 7, mm = l4 >> 3;
                cp16(aBase + (uint32_t)(mm * 36 + kk4 * 4) * 4u,
                     &A4[(size_t)(m0 + mm) * K4 + (k0 >> 2) + kk4]);
            } else {
                const int mm4 = l4 & 31, kk = l4 >> 5;
                cp16(aBase + (uint32_t)(kk * 136 + mm4 * 4) * 4u,
                     &A4[(size_t)(k0 + kk) * M4 + (m0 >> 2) + mm4]);
            }
        }
        #pragma unroll
        for (int j = 0; j < 4; ++j) {
            const int l4 = j * 256 + tid;
            if (TB == 0) {
                const int nn4 = l4 & 31, kk = l4 >> 5;
                cp16(bBase + (uint32_t)(kk * 136 + nn4 * 4) * 4u,
                     &B4[(size_t)(k0 + kk) * N4 + (n0 >> 2) + nn4]);
            } else {
                const int kk4 = l4 & 7, nn = l4 >> 3;
                cp16(bBase + (uint32_t)(nn * 36 + kk4 * 4) * 4u,
                     &B4[(size_t)(n0 + nn) * K4 + (k0 >> 2) + kk4]);
            }
        }
        asm volatile("cp.async.commit_group;\n" ::: "memory");
    };

    const int T = K >> 5;          // >= 16 for all problem GEMMs
    fill(0, 0);
    fill(1, 32);

    int stage = 0;                 // = t % 3
    for (int t = 0; t < T; ++t) {
        asm volatile("cp.async.wait_group 1;\n" ::: "memory");   // stage t ready
        __syncthreads();
        // refill stage (t+2)%3 (last read at iter t-1, ordered by the sync above)
        if (t + 2 < T) {
            int ns = stage + 2; if (ns >= 3) ns -= 3;
            fill(ns, (t + 2) * 32);
        } else {
            asm volatile("cp.async.commit_group;\n" ::: "memory"); // empty group keeps count
        }

        const uint32_t* As = sm + stage * AW;
        const uint32_t* Bs = sm + 3 * AW + stage * BW;

        #pragma unroll
        for (int ks = 0; ks < 4; ++ks) {
            const int kb = ks * 8;
            uint32_t af[4][4], bf[4][2];
            #pragma unroll
            for (int mt = 0; mt < 4; ++mt) {
                const int mb = warpM * 64 + mt * 16;
                if (TA == 0) {
                    af[mt][0] = As[(mb + g) * 36     + kb + tg];
                    af[mt][1] = As[(mb + g + 8) * 36 + kb + tg];
                    af[mt][2] = As[(mb + g) * 36     + kb + tg + 4];
                    af[mt][3] = As[(mb + g + 8) * 36 + kb + tg + 4];
                } else {
                    af[mt][0] = As[(kb + tg) * 136     + mb + g];
                    af[mt][1] = As[(kb + tg) * 136     + mb + g + 8];
                    af[mt][2] = As[(kb + tg + 4) * 136 + mb + g];
                    af[mt][3] = As[(kb + tg + 4) * 136 + mb + g + 8];
                }
            }
            #pragma unroll
            for (int nt = 0; nt < 4; ++nt) {
                const int nb = warpN * 32 + nt * 8;
                if (TB == 0) {
                    bf[nt][0] = Bs[(kb + tg) * 136     + nb + g];
                    bf[nt][1] = Bs[(kb + tg + 4) * 136 + nb + g];
                } else {
                    bf[nt][0] = Bs[(nb + g) * 36 + kb + tg];
                    bf[nt][1] = Bs[(nb + g) * 36 + kb + tg + 4];
                }
            }
            #pragma unroll
            for (int mt = 0; mt < 4; ++mt)
                #pragma unroll
                for (int nt = 0; nt < 4; ++nt) {
                    float* c = acc[mt][nt];
                    asm volatile(
                        "mma.sync.aligned.m16n8k8.row.col.f32.tf32.tf32.f32 "
                        "{%0,%1,%2,%3}, {%4,%5,%6,%7}, {%8,%9}, {%0,%1,%2,%3};\n"
                        : "+f"(c[0]), "+f"(c[1]), "+f"(c[2]), "+f"(c[3])
                        : "r"(af[mt][0]), "r"(af[mt][1]), "r"(af[mt][2]), "r"(af[mt][3]),
                          "r"(bf[nt][0]), "r"(bf[nt][1]));
                }
        }
        if (++stage >= 3) stage = 0;
    }

    // ---- epilogue ----
    float* Cb = C + (size_t)bz * sCb;
    const float* Rb = resid ? (resid + (size_t)bz * sRb) : nullptr;

    #pragma unroll
    for (int mt = 0; mt < 4; ++mt) {
        const int mb = m0 + warpM * 64 + mt * 16;
        const int r0 = mb + g, r1 = mb + g + 8;
        const float bi0 = bias ? bias[r0] : 0.f;
        const float bi1 = bias ? bias[r1] : 0.f;
        #pragma unroll
        for (int nt = 0; nt < 4; ++nt) {
            const int nn = n0 + warpN * 32 + nt * 8 + 2 * tg;
            const size_t o0 = (size_t)r0 * N + nn;
            const size_t o1 = (size_t)r1 * N + nn;
            float2 v0 = { alpha * acc[mt][nt][0] + bi0, alpha * acc[mt][nt][1] + bi0 };
            float2 v1 = { alpha * acc[mt][nt][2] + bi1, alpha * acc[mt][nt][3] + bi1 };
            if (Rb) {
                v0.x += Rb[o0]; v0.y += Rb[o0 + 1];
                v1.x += Rb[o1]; v1.y += Rb[o1 + 1];
            }
            *(float2*)&Cb[o0] = v0;
            *(float2*)&Cb[o1] = v1;
        }
    }
}

// ---------------- softmax over rows of length 4096 ----------------
__global__ void softmax4096(float* __restrict__ attn) {
    const size_t row = blockIdx.x;
    float* p = attn + row * AREA;
    const int tid = threadIdx.x;

    float4 r[4];
    #pragma unroll
    for (int i = 0; i < 4; ++i)
        r[i] = *(const float4*)&p[(tid + i * 256) * 4];

    float m = -3.0e38f;
    #pragma unroll
    for (int i = 0; i < 4; ++i)
        m = fmaxf(m, fmaxf(fmaxf(r[i].x, r[i].y), fmaxf(r[i].z, r[i].w)));
    __shared__ float red[256];
    red[tid] = m; __syncthreads();
    for (int off = 128; off > 0; off >>= 1) {
        if (tid < off) red[tid] = fmaxf(red[tid], red[tid + off]);
        __syncthreads();
    }
    m = red[0];
    __syncthreads();

    float s = 0.f;
    #pragma unroll
    for (int i = 0; i < 4; ++i) {
        r[i].x = __expf(r[i].x - m); r[i].y = __expf(r[i].y - m);
        r[i].z = __expf(r[i].z - m); r[i].w = __expf(r[i].w - m);
        s += r[i].x + r[i].y + r[i].z + r[i].w;
    }
    red[tid] = s; __syncthreads();
    for (int off = 128; off > 0; off >>= 1) {
        if (tid < off) red[tid] += red[tid + off];
        __syncthreads();
    }
    const float inv = 1.0f / red[0];

    #pragma unroll
    for (int i = 0; i < 4; ++i) {
        r[i].x *= inv; r[i].y *= inv; r[i].z *= inv; r[i].w *= inv;
        *(float4*)&p[(tid + i * 256) * 4] = r[i];
    }
}

// ---------------- launch ----------------
extern "C" void kernel_launch(void* const* d_in, const int* in_sizes, int n_in,
                              void* d_out, int out_size) {
    const float* net = (const float*)d_in[0];
    const float* gns = (const float*)d_in[1];
    const float* gnb = (const float*)d_in[2];
    const float* wq  = (const float*)d_in[3];
    const float* bq  = (const float*)d_in[4];
    const float* wk  = (const float*)d_in[5];
    const float* bk  = (const float*)d_in[6];
    const float* wv  = (const float*)d_in[7];
    const float* bv  = (const float*)d_in[8];
    const float* wo  = (const float*)d_in[9];
    const float* bo  = (const float*)d_in[10];
    float* out = (float*)d_out;

    float *xn, *q, *k, *v, *ao, *attn;
    cudaGetSymbolAddress((void**)&xn,   g_xn);
    cudaGetSymbolAddress((void**)&q,    g_q);
    cudaGetSymbolAddress((void**)&k,    g_k);
    cudaGetSymbolAddress((void**)&v,    g_v);
    cudaGetSymbolAddress((void**)&ao,   g_ao);
    cudaGetSymbolAddress((void**)&attn, g_attn);

    const size_t sX = (size_t)C_DIM * AREA;
    const size_t sA = (size_t)AREA * AREA;

    // dynamic smem: 3*(AW+BW)*4 bytes per instantiation
    const int SM00 = 3 * (128 * 36 + 32 * 136) * 4;   // 107520
    const int SM10 = 3 * (32 * 136 + 32 * 136) * 4;   // 104448
    const int SM01 = 3 * (128 * 36 + 128 * 36) * 4;   // 110592
    cudaFuncSetAttribute(gemm_p3<0, 0>, cudaFuncAttributeMaxDynamicSharedMemorySize, SM00);
    cudaFuncSetAttribute(gemm_p3<1, 0>, cudaFuncAttributeMaxDynamicSharedMemorySize, SM10);
    cudaFuncSetAttribute(gemm_p3<0, 1>, cudaFuncAttributeMaxDynamicSharedMemorySize, SM01);

    groupnorm_kernel<<<BATCH * GROUPS, 256>>>(net, gns, gnb, xn);

    dim3 blk(256);
    dim3 gProj(AREA / 128, C_DIM / 128, BATCH);   // (32, 4, 4)
    // Q/K/V: W[o,c] @ xn[c,a] + b
    gemm_p3<0, 0><<<gProj, blk, SM00>>>(wq, xn, q, C_DIM, AREA, C_DIM, 0, sX, sX, 1.f, bq, nullptr, 0);
    gemm_p3<0, 0><<<gProj, blk, SM00>>>(wk, xn, k, C_DIM, AREA, C_DIM, 0, sX, sX, 1.f, bk, nullptr, 0);
    gemm_p3<0, 0><<<gProj, blk, SM00>>>(wv, xn, v, C_DIM, AREA, C_DIM, 0, sX, sX, 1.f, bv, nullptr, 0);

    // attn[i,j] = scale * sum_c q[c,i] * k[c,j]   (TN: A stored [K,M])
    dim3 gAttn(AREA / 128, AREA / 128, BATCH);    // (32, 32, 4)
    const float scale = 0.044194173824159216f;    // 512^-0.5
    gemm_p3<1, 0><<<gAttn, blk, SM10>>>(q, k, attn, AREA, AREA, C_DIM, sX, sX, sA, scale,
                                        nullptr, nullptr, 0);

    softmax4096<<<BATCH * AREA, 256>>>(attn);

    // ao[c,i] = sum_j v[c,j] * p[i,j]   (NT: B stored [N,K])
    gemm_p3<0, 1><<<gProj, blk, SM01>>>(v, attn, ao, C_DIM, AREA, AREA, sX, sA, sX, 1.f,
                                        nullptr, nullptr, 0);

    // out = net + Wo @ ao + bo
    gemm_p3<0, 0><<<gProj, blk, SM00>>>(wo, ao, out, C_DIM, AREA, C_DIM, 0, sX, sX, 1.f,
                                        bo, net, sX);
}

// round 16
// speedup vs baseline: 1.6988x; 1.6988x over previous
#include <cuda_runtime.h>
#include <cuda_fp16.h>
#include <math.h>
#include <stdint.h>

#define C_DIM 512
#define AREA  4096
#define BATCH 4
#define GROUPS 32
#define CPG   16
#define GRP_F4 16384   // (CPG*AREA)/4 float4s per group

// ---------------- scratch (static device globals; no allocation) ----------------
// fp16 K-contiguous layouts: g_xn,g_q,g_k,g_ao are [b][a][c]; g_v is [b][c][a];
// g_attn is [b][i][j]. Weights converted once to fp16 [o][c].
__device__ __half g_xn  [(size_t)BATCH * C_DIM * AREA];
__device__ __half g_q   [(size_t)BATCH * C_DIM * AREA];
__device__ __half g_k   [(size_t)BATCH * C_DIM * AREA];
__device__ __half g_v   [(size_t)BATCH * C_DIM * AREA];
__device__ __half g_ao  [(size_t)BATCH * C_DIM * AREA];
__device__ __half g_attn[(size_t)BATCH * AREA * AREA];
__device__ __half g_w16 [4 * C_DIM * C_DIM];          // wq, wk, wv, wo

// ---------------- fp32 -> fp16 weight conversion ----------------
__global__ void f2h_kernel(const float* __restrict__ s, __half* __restrict__ d, int n) {
    const int i = blockIdx.x * blockDim.x + threadIdx.x;
    if (i < n) d[i] = __float2half_rn(s[i]);
}

// ---------------- GroupNorm + transpose to fp16 [a][c] ----------------
__global__ void groupnorm_t_kernel(const float* __restrict__ net,
                                   const float* __restrict__ gscale,
                                   const float* __restrict__ gbias,
                                   __half* __restrict__ xnt) {
    const int bg = blockIdx.x;          // 0..127
    const int b  = bg >> 5;
    const int gi = bg & 31;
    const size_t base = ((size_t)b * C_DIM + (size_t)gi * CPG) * AREA;
    const float4* src4 = (const float4*)(net + base);
    const int tid = threadIdx.x;

    float s = 0.f, ss = 0.f;
    for (int i = tid; i < GRP_F4; i += 256) {
        float4 v = src4[i];
        s  += v.x + v.y + v.z + v.w;
        ss += v.x*v.x + v.y*v.y + v.z*v.z + v.w*v.w;
    }
    __shared__ float red[512];
    red[tid] = s; red[256 + tid] = ss;
    __syncthreads();
    for (int off = 128; off > 0; off >>= 1) {
        if (tid < off) {
            red[tid]       += red[tid + off];
            red[256 + tid] += red[256 + tid + off];
        }
        __syncthreads();
    }
    const float inv_n = 1.0f / 65536.0f;
    const float mu   = red[0] * inv_n;
    const float var  = red[256] * inv_n - mu * mu;
    const float rstd = rsqrtf(var + 1e-6f);

    __shared__ float T[16 * 68];
    const int c_l = tid >> 4;
    const int a4  = tid & 15;
    const int a_l = tid >> 2;
    const int cq  = tid & 3;
    const float sc = gscale[gi * CPG + c_l] * rstd;
    const float bi = gbias[gi * CPG + c_l];

    for (int a0 = 0; a0 < AREA; a0 += 64) {
        float4 v = src4[c_l * (AREA/4) + (a0 >> 2) + a4];
        v.x = (v.x - mu) * sc + bi;
        v.y = (v.y - mu) * sc + bi;
        v.z = (v.z - mu) * sc + bi;
        v.w = (v.w - mu) * sc + bi;
        __syncthreads();
        *(float4*)&T[c_l * 68 + a4 * 4] = v;
        __syncthreads();
        float4 w;
        w.x = T[(cq * 4 + 0) * 68 + a_l];
        w.y = T[(cq * 4 + 1) * 68 + a_l];
        w.z = T[(cq * 4 + 2) * 68 + a_l];
        w.w = T[(cq * 4 + 3) * 68 + a_l];
        const size_t idx = ((size_t)b * AREA + a0 + a_l) * C_DIM + gi * CPG + cq * 4;
        *(__half2*)&xnt[idx]     = __floats2half2_rn(w.x, w.y);
        *(__half2*)&xnt[idx + 2] = __floats2half2_rn(w.z, w.w);
    }
}

// ---------------- async copy helper ----------------
__device__ __forceinline__ void cp16(uint32_t dst_smem, const void* src) {
    asm volatile("cp.async.cg.shared.global [%0], [%1], 16;\n"
                 :: "r"(dst_smem), "l"(src));
}

// ---------------- fp16 tensor-core GEMM, cp.async double-buffered ----------------
// C[m,n] = alpha * sum_k A[m][k]*B[n][k] + biasM[m] + biasN[n] + resid[m,n]
// A [M,K] fp16 row-major, B [N,K] fp16 row-major (both K-contiguous).
// Block 128x128, BK=64 halves, 256 threads (8 warps of 64x32), mma m16n8k16 f16->f32.
// Smem: [row][k] layout, 36 words (72 halves) per row -> fragment LDS.32 banks
// (4g+tg) all distinct (proven round-6 pattern). Stage = 2*128*36 words = 36864 B.
// OH=1: fp16 output; OH=0: fp32 output (+ optional resid).
template<int OH>
__global__ __launch_bounds__(256, 2)
void gemm_h(const __half* __restrict__ A, const __half* __restrict__ B,
            void* __restrict__ Cout,
            int M, int N, int K,
            size_t sAb, size_t sBb, size_t sCb,
            float alpha,
            const float* __restrict__ biasM,
            const float* __restrict__ biasN,
            const float* __restrict__ resid, size_t sRb) {
    extern __shared__ uint32_t sm[];    // 2 stages * 2 matrices * 128*36 words

    const int tid  = threadIdx.x;
    const int warp = tid >> 5;
    const int lane = tid & 31;
    const int g    = lane >> 2;     // 0..7
    const int tg   = lane & 3;      // 0..3
    const int warpM = warp >> 2;    // 0..1  (64 rows)
    const int warpN = warp & 3;     // 0..3  (32 cols)
    const int n0 = blockIdx.x * 128;
    const int m0 = blockIdx.y * 128;
    const int bz = blockIdx.z;

    const uint4* A16 = (const uint4*)(A + (size_t)bz * sAb);   // 8 halves per uint4
    const uint4* B16 = (const uint4*)(B + (size_t)bz * sBb);
    const int K8 = K >> 3;          // uint4 per row
    const uint32_t sb = (uint32_t)__cvta_generic_to_shared(sm);

    float acc[4][4][4];
    #pragma unroll
    for (int mt = 0; mt < 4; ++mt)
        #pragma unroll
        for (int nt = 0; nt < 4; ++nt)
            #pragma unroll
            for (int r = 0; r < 4; ++r) acc[mt][nt][r] = 0.f;

    // ---- async fill of one stage with ktile t (BK=64 halves = 8 uint4/row) ----
    auto fill = [&](int stage, int t) {
        const uint32_t aBase = sb + (uint32_t)stage * 36864u;
        const uint32_t bBase = aBase + 18432u;
        #pragma unroll
        for (int j = 0; j < 4; ++j) {
            const int l = j * 256 + tid;           // 0..1023
            const int row = l >> 3, ch = l & 7;
            cp16(aBase + (uint32_t)(row * 144 + ch * 16),
                 &A16[(size_t)(m0 + row) * K8 + t * 8 + ch]);
        }
        #pragma unroll
        for (int j = 0; j < 4; ++j) {
            const int l = j * 256 + tid;
            const int row = l >> 3, ch = l & 7;
            cp16(bBase + (uint32_t)(row * 144 + ch * 16),
                 &B16[(size_t)(n0 + row) * K8 + t * 8 + ch]);
        }
        asm volatile("cp.async.commit_group;\n" ::: "memory");
    };

    fill(0, 0);
    const int T = K >> 6;                 // ktiles of 64
    for (int t = 0; t < T; ++t) {
        if (t + 1 < T) {
            fill((t + 1) & 1, t + 1);
            asm volatile("cp.async.wait_group 1;\n" ::: "memory");
        } else {
            asm volatile("cp.async.wait_group 0;\n" ::: "memory");
        }
        __syncthreads();

        const uint32_t* As = sm + (t & 1) * 9216;
        const uint32_t* Bs = As + 4608;

        #pragma unroll
        for (int ks = 0; ks < 4; ++ks) {           // 4 x k16
            const int kw = ks * 8;                 // word base within row
            uint32_t af[4][4], bf[4][2];
            #pragma unroll
            for (int mt = 0; mt < 4; ++mt) {
                const int mb = warpM * 64 + mt * 16;
                af[mt][0] = As[(mb + g) * 36     + kw + tg];
                af[mt][1] = As[(mb + g + 8) * 36 + kw + tg];
                af[mt][2] = As[(mb + g) * 36     + kw + tg + 4];
                af[mt][3] = As[(mb + g + 8) * 36 + kw + tg + 4];
            }
            #pragma unroll
            for (int nt = 0; nt < 4; ++nt) {
                const int nb = warpN * 32 + nt * 8;
                bf[nt][0] = Bs[(nb + g) * 36 + kw + tg];
                bf[nt][1] = Bs[(nb + g) * 36 + kw + tg + 4];
            }
            #pragma unroll
            for (int mt = 0; mt < 4; ++mt)
                #pragma unroll
                for (int nt = 0; nt < 4; ++nt) {
                    float* c = acc[mt][nt];
                    asm volatile(
                        "mma.sync.aligned.m16n8k16.row.col.f32.f16.f16.f32 "
                        "{%0,%1,%2,%3}, {%4,%5,%6,%7}, {%8,%9}, {%0,%1,%2,%3};\n"
                        : "+f"(c[0]), "+f"(c[1]), "+f"(c[2]), "+f"(c[3])
                        : "r"(af[mt][0]), "r"(af[mt][1]), "r"(af[mt][2]), "r"(af[mt][3]),
                          "r"(bf[nt][0]), "r"(bf[nt][1]));
                }
        }
        __syncthreads();
    }

    // ---- epilogue ----
    #pragma unroll
    for (int mt = 0; mt < 4; ++mt) {
        const int mb = m0 + warpM * 64 + mt * 16;
        const int r0 = mb + g, r1 = mb + g + 8;
        const float bm0 = biasM ? biasM[r0] : 0.f;
        const float bm1 = biasM ? biasM[r1] : 0.f;
        #pragma unroll
        for (int nt = 0; nt < 4; ++nt) {
            const int nn = n0 + warpN * 32 + nt * 8 + 2 * tg;
            const float bn0 = biasN ? biasN[nn]     : 0.f;
            const float bn1 = biasN ? biasN[nn + 1] : 0.f;
            const size_t o0 = (size_t)r0 * N + nn;
            const size_t o1 = (size_t)r1 * N + nn;
            float2 v0 = { alpha * acc[mt][nt][0] + bm0 + bn0,
                          alpha * acc[mt][nt][1] + bm0 + bn1 };
            float2 v1 = { alpha * acc[mt][nt][2] + bm1 + bn0,
                          alpha * acc[mt][nt][3] + bm1 + bn1 };
            if (OH) {
                __half* Ch = (__half*)Cout + (size_t)bz * sCb;
                *(__half2*)&Ch[o0] = __floats2half2_rn(v0.x, v0.y);
                *(__half2*)&Ch[o1] = __floats2half2_rn(v1.x, v1.y);
            } else {
                float* Cf = (float*)Cout + (size_t)bz * sCb;
                if (resid) {
                    const float* Rb = resid + (size_t)bz * sRb;
                    v0.x += Rb[o0]; v0.y += Rb[o0 + 1];
                    v1.x += Rb[o1]; v1.y += Rb[o1 + 1];
                }
                *(float2*)&Cf[o0] = v0;
                *(float2*)&Cf[o1] = v1;
            }
        }
    }
}

// ---------------- softmax over fp16 rows of length 4096 ----------------
__global__ void softmax4096h(__half* __restrict__ attn) {
    const size_t row = blockIdx.x;
    __half* p = attn + row * AREA;
    const int tid = threadIdx.x;

    uint4 u[2];
    #pragma unroll
    for (int i = 0; i < 2; ++i)
        u[i] = ((const uint4*)p)[tid + i * 256];

    float f[16];
    #pragma unroll
    for (int i = 0; i < 2; ++i) {
        const __half2* h = (const __half2*)&u[i];
        #pragma unroll
        for (int j = 0; j < 4; ++j) {
            float2 t = __half22float2(h[j]);
            f[i * 8 + 2 * j]     = t.x;
            f[i * 8 + 2 * j + 1] = t.y;
        }
    }

    float m = -3.0e38f;
    #pragma unroll
    for (int i = 0; i < 16; ++i) m = fmaxf(m, f[i]);
    __shared__ float red[256];
    red[tid] = m; __syncthreads();
    for (int off = 128; off > 0; off >>= 1) {
        if (tid < off) red[tid] = fmaxf(red[tid], red[tid + off]);
        __syncthreads();
    }
    m = red[0];
    __syncthreads();

    float s = 0.f;
    #pragma unroll
    for (int i = 0; i < 16; ++i) { f[i] = __expf(f[i] - m); s += f[i]; }
    red[tid] = s; __syncthreads();
    for (int off = 128; off > 0; off >>= 1) {
        if (tid < off) red[tid] += red[tid + off];
        __syncthreads();
    }
    const float inv = 1.0f / red[0];

    #pragma unroll
    for (int i = 0; i < 2; ++i) {
        __half2* h = (__half2*)&u[i];
        #pragma unroll
        for (int j = 0; j < 4; ++j)
            h[j] = __floats2half2_rn(f[i * 8 + 2 * j] * inv, f[i * 8 + 2 * j + 1] * inv);
        ((uint4*)p)[tid + i * 256] = u[i];
    }
}

// ---------------- launch ----------------
extern "C" void kernel_launch(void* const* d_in, const int* in_sizes, int n_in,
                              void* d_out, int out_size) {
    const float* net = (const float*)d_in[0];
    const float* gns = (const float*)d_in[1];
    const float* gnb = (const float*)d_in[2];
    const float* wq  = (const float*)d_in[3];
    const float* bq  = (const float*)d_in[4];
    const float* wk  = (const float*)d_in[5];
    const float* bk  = (const float*)d_in[6];
    const float* wv  = (const float*)d_in[7];
    const float* bv  = (const float*)d_in[8];
    const float* wo  = (const float*)d_in[9];
    const float* bo  = (const float*)d_in[10];
    float* out = (float*)d_out;

    __half *xn, *q, *k, *v, *ao, *attn, *w16;
    cudaGetSymbolAddress((void**)&xn,   g_xn);
    cudaGetSymbolAddress((void**)&q,    g_q);
    cudaGetSymbolAddress((void**)&k,    g_k);
    cudaGetSymbolAddress((void**)&v,    g_v);
    cudaGetSymbolAddress((void**)&ao,   g_ao);
    cudaGetSymbolAddress((void**)&attn, g_attn);
    cudaGetSymbolAddress((void**)&w16,  g_w16);
    __half* wq16 = w16;
    __half* wk16 = w16 + (size_t)C_DIM * C_DIM;
    __half* wv16 = w16 + (size_t)2 * C_DIM * C_DIM;
    __half* wo16 = w16 + (size_t)3 * C_DIM * C_DIM;

    const size_t sX = (size_t)C_DIM * AREA;
    const size_t sA = (size_t)AREA * AREA;

    const int SMEM = 2 * 36864;    // 73728 B dynamic
    cudaFuncSetAttribute(gemm_h<0>, cudaFuncAttributeMaxDynamicSharedMemorySize, SMEM);
    cudaFuncSetAttribute(gemm_h<1>, cudaFuncAttributeMaxDynamicSharedMemorySize, SMEM);

    // weight conversion (262144 elems each)
    const int NW = C_DIM * C_DIM;
    f2h_kernel<<<NW / 256, 256>>>(wq, wq16, NW);
    f2h_kernel<<<NW / 256, 256>>>(wk, wk16, NW);
    f2h_kernel<<<NW / 256, 256>>>(wv, wv16, NW);
    f2h_kernel<<<NW / 256, 256>>>(wo, wo16, NW);

    // GroupNorm -> xn[b][a][c] fp16
    groupnorm_t_kernel<<<BATCH * GROUPS, 256>>>(net, gns, gnb, xn);

    dim3 blk(256);
    dim3 gAN(C_DIM / 128, AREA / 128, BATCH);   // M=4096(a), N=512(o)
    dim3 gNA(AREA / 128, C_DIM / 128, BATCH);   // M=512(o),  N=4096(a)
    dim3 gAA(AREA / 128, AREA / 128, BATCH);

    // Q/K: q[a][o] = sum_c xn[a][c]*wq[o][c] + bq[o]   (biasN)
    gemm_h<1><<<gAN, blk, SMEM>>>(xn, wq16, q, AREA, C_DIM, C_DIM, sX, 0, sX, 1.f,
                                  nullptr, bq, nullptr, 0);
    gemm_h<1><<<gAN, blk, SMEM>>>(xn, wk16, k, AREA, C_DIM, C_DIM, sX, 0, sX, 1.f,
                                  nullptr, bk, nullptr, 0);
    // V: v[o][a] = sum_c wv[o][c]*xn[a][c] + bv[o]     (biasM)
    gemm_h<1><<<gNA, blk, SMEM>>>(wv16, xn, v, C_DIM, AREA, C_DIM, 0, sX, sX, 1.f,
                                  bv, nullptr, nullptr, 0);

    // attn[i][j] = scale * sum_c q[i][c]*k[j][c]
    const float scale = 0.044194173824159216f;    // 512^-0.5
    gemm_h<1><<<gAA, blk, SMEM>>>(q, k, attn, AREA, AREA, C_DIM, sX, sX, sA, scale,
                                  nullptr, nullptr, nullptr, 0);

    softmax4096h<<<BATCH * AREA, 256>>>(attn);

    // ao[i][c] = sum_j attn[i][j] * v[c][j]
    gemm_h<1><<<gAN, blk, SMEM>>>(attn, v, ao, AREA, C_DIM, AREA, sA, sX, sX, 1.f,
                                  nullptr, nullptr, nullptr, 0);

    // out[o][a] = sum_c wo[o][c]*ao[a][c] + bo[o] + net[o][a]   (fp32 + resid)
    gemm_h<0><<<gNA, blk, SMEM>>>(wo16, ao, out, C_DIM, AREA, C_DIM, 0, sX, sX, 1.f,
                                  bo, nullptr, net, sX);
}

// round 17
// speedup vs baseline: 1.8119x; 1.0666x over previous
#include <cuda_runtime.h>
#include <cuda_fp16.h>
#include <math.h>
#include <stdint.h>

#define C_DIM 512
#define AREA  4096
#define BATCH 4
#define GROUPS 32
#define CPG   16
#define GRP_F4 16384   // (CPG*AREA)/4 float4s per group

// ---------------- scratch (static device globals; no allocation) ----------------
// fp16 K-contiguous layouts: g_xn,g_q,g_k,g_ao are [b][a][c]; g_v is [b][c][a];
// g_attn is [b][i][j]. Weights converted once to fp16 [o][c].
__device__ __half g_xn  [(size_t)BATCH * C_DIM * AREA];
__device__ __half g_q   [(size_t)BATCH * C_DIM * AREA];
__device__ __half g_k   [(size_t)BATCH * C_DIM * AREA];
__device__ __half g_v   [(size_t)BATCH * C_DIM * AREA];
__device__ __half g_ao  [(size_t)BATCH * C_DIM * AREA];
__device__ __half g_attn[(size_t)BATCH * AREA * AREA];
__device__ __half g_w16 [4 * C_DIM * C_DIM];          // wq, wk, wv, wo

// ---------------- fp32 -> fp16 conversion of all four weight matrices ----------------
__global__ void f2h4_kernel(const float* __restrict__ w0, const float* __restrict__ w1,
                            const float* __restrict__ w2, const float* __restrict__ w3,
                            __half* __restrict__ d) {
    const int i = blockIdx.x * blockDim.x + threadIdx.x;   // 0 .. 4*2^18-1
    const int m = i >> 18;
    const int o = i & ((C_DIM * C_DIM) - 1);
    const float* s = (m == 0) ? w0 : (m == 1) ? w1 : (m == 2) ? w2 : w3;
    d[i] = __float2half_rn(s[o]);
}

// ---------------- GroupNorm + transpose to fp16 [a][c] ----------------
__global__ void groupnorm_t_kernel(const float* __restrict__ net,
                                   const float* __restrict__ gscale,
                                   const float* __restrict__ gbias,
                                   __half* __restrict__ xnt) {
    const int bg = blockIdx.x;          // 0..127
    const int b  = bg >> 5;
    const int gi = bg & 31;
    const size_t base = ((size_t)b * C_DIM + (size_t)gi * CPG) * AREA;
    const float4* src4 = (const float4*)(net + base);
    const int tid = threadIdx.x;

    float s = 0.f, ss = 0.f;
    for (int i = tid; i < GRP_F4; i += 256) {
        float4 v = src4[i];
        s  += v.x + v.y + v.z + v.w;
        ss += v.x*v.x + v.y*v.y + v.z*v.z + v.w*v.w;
    }
    __shared__ float red[512];
    red[tid] = s; red[256 + tid] = ss;
    __syncthreads();
    for (int off = 128; off > 0; off >>= 1) {
        if (tid < off) {
            red[tid]       += red[tid + off];
            red[256 + tid] += red[256 + tid + off];
        }
        __syncthreads();
    }
    const float inv_n = 1.0f / 65536.0f;
    const float mu   = red[0] * inv_n;
    const float var  = red[256] * inv_n - mu * mu;
    const float rstd = rsqrtf(var + 1e-6f);

    __shared__ float T[16 * 68];
    const int c_l = tid >> 4;
    const int a4  = tid & 15;
    const int a_l = tid >> 2;
    const int cq  = tid & 3;
    const float sc = gscale[gi * CPG + c_l] * rstd;
    const float bi = gbias[gi * CPG + c_l];

    for (int a0 = 0; a0 < AREA; a0 += 64) {
        float4 v = src4[c_l * (AREA/4) + (a0 >> 2) + a4];
        v.x = (v.x - mu) * sc + bi;
        v.y = (v.y - mu) * sc + bi;
        v.z = (v.z - mu) * sc + bi;
        v.w = (v.w - mu) * sc + bi;
        __syncthreads();
        *(float4*)&T[c_l * 68 + a4 * 4] = v;
        __syncthreads();
        float4 w;
        w.x = T[(cq * 4 + 0) * 68 + a_l];
        w.y = T[(cq * 4 + 1) * 68 + a_l];
        w.z = T[(cq * 4 + 2) * 68 + a_l];
        w.w = T[(cq * 4 + 3) * 68 + a_l];
        const size_t idx = ((size_t)b * AREA + a0 + a_l) * C_DIM + gi * CPG + cq * 4;
        *(__half2*)&xnt[idx]     = __floats2half2_rn(w.x, w.y);
        *(__half2*)&xnt[idx + 2] = __floats2half2_rn(w.z, w.w);
    }
}

// ---------------- async copy helper ----------------
__device__ __forceinline__ void cp16(uint32_t dst_smem, const void* src) {
    asm volatile("cp.async.cg.shared.global [%0], [%1], 16;\n"
                 :: "r"(dst_smem), "l"(src));
}

// ---------------- fp16 tensor-core GEMM, 64x64 warp tiles ----------------
// C[m,n] = alpha * sum_k A[m][k]*B[n][k] + biasM[m] + biasN[n] + resid[m,n]
// A [M,K] fp16 row-major, B [N,K] fp16 row-major (both K-contiguous).
// Block 128x128, BK=64 halves, 128 threads = 4 warps of 64x64 (A re-read 2x,
// B re-read 2x -> 96KB crossbar per ktile vs 512 tensor-cyc: ~68% ceiling).
// Smem [row][k]: 36 words (72 halves) per row -> fragment LDS.32 banks (4g+tg)
// distinct. Stage = 2*128*36 words = 36864 B; 2 stages, cp.async double buffer.
// OH=1: fp16 output; OH=0: fp32 output (+ optional resid).
template<int OH>
__global__ __launch_bounds__(128, 2)
void gemm_h(const __half* __restrict__ A, const __half* __restrict__ B,
            void* __restrict__ Cout,
            int M, int N, int K,
            size_t sAb, size_t sBb, size_t sCb,
            float alpha,
            const float* __restrict__ biasM,
            const float* __restrict__ biasN,
            const float* __restrict__ resid, size_t sRb) {
    extern __shared__ uint32_t sm[];    // 2 stages * 2 matrices * 128*36 words

    const int tid  = threadIdx.x;
    const int warp = tid >> 5;
    const int lane = tid & 31;
    const int g    = lane >> 2;     // 0..7
    const int tg   = lane & 3;      // 0..3
    const int warpM = warp >> 1;    // 0..1  (64 rows)
    const int warpN = warp & 1;     // 0..1  (64 cols)
    const int n0 = blockIdx.x * 128;
    const int m0 = blockIdx.y * 128;
    const int bz = blockIdx.z;

    const uint4* A16 = (const uint4*)(A + (size_t)bz * sAb);   // 8 halves per uint4
    const uint4* B16 = (const uint4*)(B + (size_t)bz * sBb);
    const int K8 = K >> 3;          // uint4 per row
    const uint32_t sb = (uint32_t)__cvta_generic_to_shared(sm);

    float acc[4][8][4];
    #pragma unroll
    for (int mt = 0; mt < 4; ++mt)
        #pragma unroll
        for (int nt = 0; nt < 8; ++nt)
            #pragma unroll
            for (int r = 0; r < 4; ++r) acc[mt][nt][r] = 0.f;

    // ---- async fill of one stage with ktile t (BK=64 halves = 8 uint4/row) ----
    auto fill = [&](int stage, int t) {
        const uint32_t aBase = sb + (uint32_t)stage * 36864u;
        const uint32_t bBase = aBase + 18432u;
        #pragma unroll
        for (int j = 0; j < 8; ++j) {
            const int l = j * 128 + tid;           // 0..1023
            const int row = l >> 3, ch = l & 7;
            cp16(aBase + (uint32_t)(row * 144 + ch * 16),
                 &A16[(size_t)(m0 + row) * K8 + t * 8 + ch]);
        }
        #pragma unroll
        for (int j = 0; j < 8; ++j) {
            const int l = j * 128 + tid;
            const int row = l >> 3, ch = l & 7;
            cp16(bBase + (uint32_t)(row * 144 + ch * 16),
                 &B16[(size_t)(n0 + row) * K8 + t * 8 + ch]);
        }
        asm volatile("cp.async.commit_group;\n" ::: "memory");
    };

    fill(0, 0);
    const int T = K >> 6;                 // ktiles of 64
    for (int t = 0; t < T; ++t) {
        if (t + 1 < T) {
            fill((t + 1) & 1, t + 1);
            asm volatile("cp.async.wait_group 1;\n" ::: "memory");
        } else {
            asm volatile("cp.async.wait_group 0;\n" ::: "memory");
        }
        __syncthreads();

        const uint32_t* As = sm + (t & 1) * 9216;
        const uint32_t* Bs = As + 4608;

        #pragma unroll
        for (int ks = 0; ks < 4; ++ks) {           // 4 x k16
            const int kw = ks * 8;                 // word base within row
            uint32_t af[4][4], bf[8][2];
            #pragma unroll
            for (int mt = 0; mt < 4; ++mt) {
                const int mb = warpM * 64 + mt * 16;
                af[mt][0] = As[(mb + g) * 36     + kw + tg];
                af[mt][1] = As[(mb + g + 8) * 36 + kw + tg];
                af[mt][2] = As[(mb + g) * 36     + kw + tg + 4];
                af[mt][3] = As[(mb + g + 8) * 36 + kw + tg + 4];
            }
            #pragma unroll
            for (int nt = 0; nt < 8; ++nt) {
                const int nb = warpN * 64 + nt * 8;
                bf[nt][0] = Bs[(nb + g) * 36 + kw + tg];
                bf[nt][1] = Bs[(nb + g) * 36 + kw + tg + 4];
            }
            #pragma unroll
            for (int mt = 0; mt < 4; ++mt)
                #pragma unroll
                for (int nt = 0; nt < 8; ++nt) {
                    float* c = acc[mt][nt];
                    asm volatile(
                        "mma.sync.aligned.m16n8k16.row.col.f32.f16.f16.f32 "
                        "{%0,%1,%2,%3}, {%4,%5,%6,%7}, {%8,%9}, {%0,%1,%2,%3};\n"
                        : "+f"(c[0]), "+f"(c[1]), "+f"(c[2]), "+f"(c[3])
                        : "r"(af[mt][0]), "r"(af[mt][1]), "r"(af[mt][2]), "r"(af[mt][3]),
                          "r"(bf[nt][0]), "r"(bf[nt][1]));
                }
        }
        __syncthreads();
    }

    // ---- epilogue ----
    #pragma unroll
    for (int mt = 0; mt < 4; ++mt) {
        const int mb = m0 + warpM * 64 + mt * 16;
        const int r0 = mb + g, r1 = mb + g + 8;
        const float bm0 = biasM ? biasM[r0] : 0.f;
        const float bm1 = biasM ? biasM[r1] : 0.f;
        #pragma unroll
        for (int nt = 0; nt < 8; ++nt) {
            const int nn = n0 + warpN * 64 + nt * 8 + 2 * tg;
            const float bn0 = biasN ? biasN[nn]     : 0.f;
            const float bn1 = biasN ? biasN[nn + 1] : 0.f;
            const size_t o0 = (size_t)r0 * N + nn;
            const size_t o1 = (size_t)r1 * N + nn;
            float2 v0 = { alpha * acc[mt][nt][0] + bm0 + bn0,
                          alpha * acc[mt][nt][1] + bm0 + bn1 };
            float2 v1 = { alpha * acc[mt][nt][2] + bm1 + bn0,
                          alpha * acc[mt][nt][3] + bm1 + bn1 };
            if (OH) {
                __half* Ch = (__half*)Cout + (size_t)bz * sCb;
                *(__half2*)&Ch[o0] = __floats2half2_rn(v0.x, v0.y);
                *(__half2*)&Ch[o1] = __floats2half2_rn(v1.x, v1.y);
            } else {
                float* Cf = (float*)Cout + (size_t)bz * sCb;
                if (resid) {
                    const float* Rb = resid + (size_t)bz * sRb;
                    v0.x += Rb[o0]; v0.y += Rb[o0 + 1];
                    v1.x += Rb[o1]; v1.y += Rb[o1 + 1];
                }
                *(float2*)&Cf[o0] = v0;
                *(float2*)&Cf[o1] = v1;
            }
        }
    }
}

// ---------------- softmax over fp16 rows of length 4096 ----------------
__global__ void softmax4096h(__half* __restrict__ attn) {
    const size_t row = blockIdx.x;
    __half* p = attn + row * AREA;
    const int tid = threadIdx.x;

    uint4 u[2];
    #pragma unroll
    for (int i = 0; i < 2; ++i)
        u[i] = ((const uint4*)p)[tid + i * 256];

    float f[16];
    #pragma unroll
    for (int i = 0; i < 2; ++i) {
        const __half2* h = (const __half2*)&u[i];
        #pragma unroll
        for (int j = 0; j < 4; ++j) {
            float2 t = __half22float2(h[j]);
            f[i * 8 + 2 * j]     = t.x;
            f[i * 8 + 2 * j + 1] = t.y;
        }
    }

    float m = -3.0e38f;
    #pragma unroll
    for (int i = 0; i < 16; ++i) m = fmaxf(m, f[i]);
    __shared__ float red[256];
    red[tid] = m; __syncthreads();
    for (int off = 128; off > 0; off >>= 1) {
        if (tid < off) red[tid] = fmaxf(red[tid], red[tid + off]);
        __syncthreads();
    }
    m = red[0];
    __syncthreads();

    float s = 0.f;
    #pragma unroll
    for (int i = 0; i < 16; ++i) { f[i] = __expf(f[i] - m); s += f[i]; }
    red[tid] = s; __syncthreads();
    for (int off = 128; off > 0; off >>= 1) {
        if (tid < off) red[tid] += red[tid + off];
        __syncthreads();
    }
    const float inv = 1.0f / red[0];

    #pragma unroll
    for (int i = 0; i < 2; ++i) {
        __half2* h = (__half2*)&u[i];
        #pragma unroll
        for (int j = 0; j < 4; ++j)
            h[j] = __floats2half2_rn(f[i * 8 + 2 * j] * inv, f[i * 8 + 2 * j + 1] * inv);
        ((uint4*)p)[tid + i * 256] = u[i];
    }
}

// ---------------- launch ----------------
extern "C" void kernel_launch(void* const* d_in, const int* in_sizes, int n_in,
                              void* d_out, int out_size) {
    const float* net = (const float*)d_in[0];
    const float* gns = (const float*)d_in[1];
    const float* gnb = (const float*)d_in[2];
    const float* wq  = (const float*)d_in[3];
    const float* bq  = (const float*)d_in[4];
    const float* wk  = (const float*)d_in[5];
    const float* bk  = (const float*)d_in[6];
    const float* wv  = (const float*)d_in[7];
    const float* bv  = (const float*)d_in[8];
    const float* wo  = (const float*)d_in[9];
    const float* bo  = (const float*)d_in[10];
    float* out = (float*)d_out;

    __half *xn, *q, *k, *v, *ao, *attn, *w16;
    cudaGetSymbolAddress((void**)&xn,   g_xn);
    cudaGetSymbolAddress((void**)&q,    g_q);
    cudaGetSymbolAddress((void**)&k,    g_k);
    cudaGetSymbolAddress((void**)&v,    g_v);
    cudaGetSymbolAddress((void**)&ao,   g_ao);
    cudaGetSymbolAddress((void**)&attn, g_attn);
    cudaGetSymbolAddress((void**)&w16,  g_w16);
    __half* wq16 = w16;
    __half* wk16 = w16 + (size_t)C_DIM * C_DIM;
    __half* wv16 = w16 + (size_t)2 * C_DIM * C_DIM;
    __half* wo16 = w16 + (size_t)3 * C_DIM * C_DIM;

    const size_t sX = (size_t)C_DIM * AREA;
    const size_t sA = (size_t)AREA * AREA;

    const int SMEM = 2 * 36864;    // 73728 B dynamic
    cudaFuncSetAttribute(gemm_h<0>, cudaFuncAttributeMaxDynamicSharedMemorySize, SMEM);
    cudaFuncSetAttribute(gemm_h<1>, cudaFuncAttributeMaxDynamicSharedMemorySize, SMEM);

    // weight conversion: all four matrices in one launch (4 * 2^18 elements)
    f2h4_kernel<<<4 * C_DIM * C_DIM / 256, 256>>>(wq, wk, wv, wo, w16);

    // GroupNorm -> xn[b][a][c] fp16
    groupnorm_t_kernel<<<BATCH * GROUPS, 256>>>(net, gns, gnb, xn);

    dim3 blk(128);
    dim3 gAN(C_DIM / 128, AREA / 128, BATCH);   // M=4096(a), N=512(o)
    dim3 gNA(AREA / 128, C_DIM / 128, BATCH);   // M=512(o),  N=4096(a)
    dim3 gAA(AREA / 128, AREA / 128, BATCH);

    // Q/K: q[a][o] = sum_c xn[a][c]*wq[o][c] + bq[o]   (biasN)
    gemm_h<1><<<gAN, blk, SMEM>>>(xn, wq16, q, AREA, C_DIM, C_DIM, sX, 0, sX, 1.f,
                                  nullptr, bq, nullptr, 0);
    gemm_h<1><<<gAN, blk, SMEM>>>(xn, wk16, k, AREA, C_DIM, C_DIM, sX, 0, sX, 1.f,
                                  nullptr, bk, nullptr, 0);
    // V: v[o][a] = sum_c wv[o][c]*xn[a][c] + bv[o]     (biasM)
    gemm_h<1><<<gNA, blk, SMEM>>>(wv16, xn, v, C_DIM, AREA, C_DIM, 0, sX, sX, 1.f,
                                  bv, nullptr, nullptr, 0);

    // attn[i][j] = scale * sum_c q[i][c]*k[j][c]
    const float scale = 0.044194173824159216f;    // 512^-0.5
    gemm_h<1><<<gAA, blk, SMEM>>>(q, k, attn, AREA, AREA, C_DIM, sX, sX, sA, scale,
                                  nullptr, nullptr, nullptr, 0);

    softmax4096h<<<BATCH * AREA, 256>>>(attn);

    // ao[i][c] = sum_j attn[i][j] * v[c][j]
    gemm_h<1><<<gAN, blk, SMEM>>>(attn, v, ao, AREA, C_DIM, AREA, sA, sX, sX, 1.f,
                                  nullptr, nullptr, nullptr, 0);

    // out[o][a] = sum_c wo[o][c]*ao[a][c] + bo[o] + net[o][a]   (fp32 + resid)
    gemm_h<0><<<gNA, blk, SMEM>>>(wo16, ao, out, C_DIM, AREA, C_DIM, 0, sX, sX, 1.f,
                                  bo, nullptr, net, sX);
}